// round 12
// baseline (speedup 1.0000x reference)
#include <cuda_runtime.h>
#include <math.h>

#define B_    32
#define S_    512
#define IN_   1024
#define H_    1024
#define OUT_  1024
#define G4_   4096   // 4*H

// ---------------- scratch (device globals; no allocation allowed) ----------
__device__ float g_GX[(size_t)S_ * B_ * G4_];   // [t][b][4H] pre-activations from x-part (+bias)
__device__ float g_HS[(size_t)B_ * S_ * H_];    // [b][t][H]  hidden outputs
__device__ float g_hbuf[2][B_ * H_];            // double-buffered h
__device__ float g_c[B_ * H_];                  // cell state

// ---------------- f32x2 packed helpers ------------------------------------
__device__ __forceinline__ unsigned long long splat2(float v) {
    unsigned long long r;
    asm("mov.b64 %0, {%1, %1};" : "=l"(r) : "f"(v));
    return r;
}
__device__ __forceinline__ unsigned long long pack2(float lo, float hi) {
    unsigned long long r;
    asm("mov.b64 %0, {%1, %2};" : "=l"(r) : "f"(lo), "f"(hi));
    return r;
}
__device__ __forceinline__ void fma2(unsigned long long& d, unsigned long long a, unsigned long long b) {
    asm("fma.rn.f32x2 %0, %1, %2, %0;" : "+l"(d) : "l"(a), "l"(b));
}
__device__ __forceinline__ float2 unpack2(unsigned long long v) {
    float2 r;
    asm("mov.b64 {%0, %1}, %2;" : "=f"(r.x), "=f"(r.y) : "l"(v));
    return r;
}

// ---------------- init: zero h0 and c0 ------------------------------------
__global__ void init_state_kernel() {
    int i = blockIdx.x * blockDim.x + threadIdx.x;
    if (i < B_ * H_) {
        g_hbuf[0][i] = 0.0f;
        g_c[i] = 0.0f;
    }
}

// ---------------- Phase 1: GX[t*32+b][n] = x[b,t,:] @ Wx[n,:].T + bias[n] --
// M = B*S = 16384 (row m = b*S + t), N = 4096 (n = g*1024 + j), K = 1024.
// 64x64 tile, BK=16, 256 threads, 4x4 per thread (f32x2 packed along N).
__global__ __launch_bounds__(256) void gx_gemm(
    const float* __restrict__ x,
    const float* __restrict__ Wf, const float* __restrict__ Wi,
    const float* __restrict__ Wc, const float* __restrict__ Wo,
    const float* __restrict__ bf, const float* __restrict__ bi,
    const float* __restrict__ bc, const float* __restrict__ bo)
{
    __shared__ float As[16][68];
    __shared__ float Bs[16][68];

    const int tid = threadIdx.x;
    const int m0 = blockIdx.y * 64;
    const int n0 = blockIdx.x * 64;
    const int tx = tid & 15;
    const int ty = tid >> 4;

    // loader mapping: one float4 along K per thread
    const int lrow = tid >> 2;          // 0..63
    const int lkq  = (tid & 3) * 4;     // 0,4,8,12

    const int nl = n0 + lrow;
    const int gg = nl >> 10;
    const int jw = nl & 1023;
    const float* Wg = (gg == 0) ? Wf : ((gg == 1) ? Wi : ((gg == 2) ? Wc : Wo));
    const float* wrow = Wg + (size_t)jw * 2048 + 1024;   // x-part columns
    const float* arow = x + (size_t)(m0 + lrow) * 1024;

    unsigned long long acc[4][2];
#pragma unroll
    for (int r = 0; r < 4; ++r) { acc[r][0] = 0ull; acc[r][1] = 0ull; }

    for (int k0 = 0; k0 < 1024; k0 += 16) {
        float4 av = *(const float4*)(arow + k0 + lkq);
        float4 bv = *(const float4*)(wrow + k0 + lkq);
        As[lkq + 0][lrow] = av.x; As[lkq + 1][lrow] = av.y;
        As[lkq + 2][lrow] = av.z; As[lkq + 3][lrow] = av.w;
        Bs[lkq + 0][lrow] = bv.x; Bs[lkq + 1][lrow] = bv.y;
        Bs[lkq + 2][lrow] = bv.z; Bs[lkq + 3][lrow] = bv.w;
        __syncthreads();
#pragma unroll
        for (int k = 0; k < 16; ++k) {
            float4 a4 = *(const float4*)&As[k][ty * 4];
            ulonglong2 b2 = *(const ulonglong2*)&Bs[k][tx * 4];
            unsigned long long a0 = splat2(a4.x);
            unsigned long long a1 = splat2(a4.y);
            unsigned long long a2 = splat2(a4.z);
            unsigned long long a3 = splat2(a4.w);
            fma2(acc[0][0], a0, b2.x); fma2(acc[0][1], a0, b2.y);
            fma2(acc[1][0], a1, b2.x); fma2(acc[1][1], a1, b2.y);
            fma2(acc[2][0], a2, b2.x); fma2(acc[2][1], a2, b2.y);
            fma2(acc[3][0], a3, b2.x); fma2(acc[3][1], a3, b2.y);
        }
        __syncthreads();
    }

    float bias[4];
#pragma unroll
    for (int c = 0; c < 4; ++c) {
        int n = n0 + tx * 4 + c;
        int g2 = n >> 10, j2 = n & 1023;
        const float* bb = (g2 == 0) ? bf : ((g2 == 1) ? bi : ((g2 == 2) ? bc : bo));
        bias[c] = bb[j2];
    }
#pragma unroll
    for (int r = 0; r < 4; ++r) {
        int m = m0 + ty * 4 + r;
        int b  = m >> 9;        // m / 512
        int tt = m & 511;       // m % 512
        size_t row = (size_t)tt * B_ + b;
        float2 p0 = unpack2(acc[r][0]);
        float2 p1 = unpack2(acc[r][1]);
        float4 v = make_float4(p0.x + bias[0], p0.y + bias[1],
                               p1.x + bias[2], p1.y + bias[3]);
        *(float4*)&g_GX[row * G4_ + n0 + tx * 4] = v;
    }
}

// ---------------- Phase 2: one recurrent LSTM step -------------------------
// pre[g,b,j] = h @ Wh[g,j,:].T + GX[t,b,g*H+j]; then cell update.
// grid = 128 blocks (8 hidden cols x 4 gates per block), 256 threads.
// f32x2 packing along K (even/odd partial sums). h read via smem broadcast,
// weights streamed straight from L2 (16MB of Wh stays L2-resident).
__global__ __launch_bounds__(256) void lstm_step(
    int t,
    const float* __restrict__ Wf, const float* __restrict__ Wi,
    const float* __restrict__ Wc, const float* __restrict__ Wo)
{
    __shared__ float hs[32][256];
    __shared__ float pre[4][32][8];

    const float* __restrict__ hin  = g_hbuf[t & 1];
    float* __restrict__       hout = g_hbuf[(t + 1) & 1];

    const int tid = threadIdx.x;
    const int col = tid & 31;        // 0..31 : (gate, jj)
    const int bg  = tid >> 5;        // 0..7  : batch group (4 rows each)
    const int g   = col >> 3;
    const int jj  = col & 7;
    const int j0  = blockIdx.x * 8;
    const int j   = j0 + jj;

    const float* __restrict__ W =
        (g == 0) ? Wf : ((g == 1) ? Wi : ((g == 2) ? Wc : Wo));
    const float* __restrict__ wrow = W + (size_t)j * 2048;   // h-part columns [0,1024)

    unsigned long long acc[4];
    {
        const float* gxr = g_GX + (size_t)t * B_ * G4_ + g * H_ + j;
#pragma unroll
        for (int i = 0; i < 4; ++i) {
            float v = gxr[(size_t)(bg * 4 + i) * G4_];
            acc[i] = pack2(v, 0.0f);
        }
    }

    for (int kb = 0; kb < 1024; kb += 256) {
        // cooperative load of h tile: 32 rows x 256 k = 2048 float4 / 256 thr = 8 each
#pragma unroll
        for (int u = 0; u < 8; ++u) {
            int idx = tid + u * 256;
            int r = idx >> 6;          // 0..31
            int c = idx & 63;          // 0..63 (float4 index)
            *(float4*)&hs[r][c * 4] =
                *(const float4*)&hin[r * 1024 + kb + c * 4];
        }
        __syncthreads();
#pragma unroll 8
        for (int kk = 0; kk < 256; kk += 4) {
            ulonglong2 w2 = *(const ulonglong2*)&wrow[kb + kk];
#pragma unroll
            for (int i = 0; i < 4; ++i) {
                ulonglong2 h2 = *(const ulonglong2*)&hs[bg * 4 + i][kk];
                fma2(acc[i], h2.x, w2.x);
                fma2(acc[i], h2.y, w2.y);
            }
        }
        __syncthreads();
    }

#pragma unroll
    for (int i = 0; i < 4; ++i) {
        float2 p = unpack2(acc[i]);
        pre[g][bg * 4 + i][jj] = p.x + p.y;
    }
    __syncthreads();

    // cell update: 256 threads = 32 batch x 8 cols, one (b, j) each
    const int b2  = tid >> 3;
    const int jj2 = tid & 7;
    const int j2  = j0 + jj2;
    float pf = pre[0][b2][jj2];
    float pi = pre[1][b2][jj2];
    float pc = pre[2][b2][jj2];
    float po = pre[3][b2][jj2];
    float fg = 1.0f / (1.0f + expf(-pf));
    float ig = 1.0f / (1.0f + expf(-pi));
    float cg = tanhf(pc);
    float og = 1.0f / (1.0f + expf(-po));
    float cold = g_c[b2 * H_ + j2];
    float cn = fg * cold + ig * cg;
    float hn = og * tanhf(cn);
    g_c[b2 * H_ + j2]  = cn;
    hout[b2 * H_ + j2] = hn;
    g_HS[((size_t)b2 * S_ + t) * H_ + j2] = hn;
}

// ---------------- Phase 3: out[m][n] = HS[m,:] @ Wfc[n,:].T + bfc[n] --------
// M = 16384 (m = b*S + t matches output layout), N = 1024, K = 1024.
__global__ __launch_bounds__(256) void fc_gemm(
    const float* __restrict__ Wfc, const float* __restrict__ bfc,
    float* __restrict__ out)
{
    __shared__ float As[16][68];
    __shared__ float Bs[16][68];

    const int tid = threadIdx.x;
    const int m0 = blockIdx.y * 64;
    const int n0 = blockIdx.x * 64;
    const int tx = tid & 15;
    const int ty = tid >> 4;

    const int lrow = tid >> 2;
    const int lkq  = (tid & 3) * 4;

    const float* wrow = Wfc + (size_t)(n0 + lrow) * 1024;
    const float* arow = g_HS + (size_t)(m0 + lrow) * 1024;

    unsigned long long acc[4][2];
#pragma unroll
    for (int r = 0; r < 4; ++r) { acc[r][0] = 0ull; acc[r][1] = 0ull; }

    for (int k0 = 0; k0 < 1024; k0 += 16) {
        float4 av = *(const float4*)(arow + k0 + lkq);
        float4 bv = *(const float4*)(wrow + k0 + lkq);
        As[lkq + 0][lrow] = av.x; As[lkq + 1][lrow] = av.y;
        As[lkq + 2][lrow] = av.z; As[lkq + 3][lrow] = av.w;
        Bs[lkq + 0][lrow] = bv.x; Bs[lkq + 1][lrow] = bv.y;
        Bs[lkq + 2][lrow] = bv.z; Bs[lkq + 3][lrow] = bv.w;
        __syncthreads();
#pragma unroll
        for (int k = 0; k < 16; ++k) {
            float4 a4 = *(const float4*)&As[k][ty * 4];
            ulonglong2 b2 = *(const ulonglong2*)&Bs[k][tx * 4];
            unsigned long long a0 = splat2(a4.x);
            unsigned long long a1 = splat2(a4.y);
            unsigned long long a2 = splat2(a4.z);
            unsigned long long a3 = splat2(a4.w);
            fma2(acc[0][0], a0, b2.x); fma2(acc[0][1], a0, b2.y);
            fma2(acc[1][0], a1, b2.x); fma2(acc[1][1], a1, b2.y);
            fma2(acc[2][0], a2, b2.x); fma2(acc[2][1], a2, b2.y);
            fma2(acc[3][0], a3, b2.x); fma2(acc[3][1], a3, b2.y);
        }
        __syncthreads();
    }

    float bias[4];
#pragma unroll
    for (int c = 0; c < 4; ++c) bias[c] = bfc[n0 + tx * 4 + c];

#pragma unroll
    for (int r = 0; r < 4; ++r) {
        int m = m0 + ty * 4 + r;
        float2 p0 = unpack2(acc[r][0]);
        float2 p1 = unpack2(acc[r][1]);
        float4 v = make_float4(p0.x + bias[0], p0.y + bias[1],
                               p1.x + bias[2], p1.y + bias[3]);
        *(float4*)&out[(size_t)m * OUT_ + n0 + tx * 4] = v;
    }
}

// ---------------- launch ----------------------------------------------------
extern "C" void kernel_launch(void* const* d_in, const int* in_sizes, int n_in,
                              void* d_out, int out_size) {
    (void)in_sizes; (void)n_in; (void)out_size;
    const float* x   = (const float*)d_in[0];
    const float* Wf  = (const float*)d_in[1];
    const float* bf  = (const float*)d_in[2];
    const float* Wi  = (const float*)d_in[3];
    const float* bi  = (const float*)d_in[4];
    const float* Wc  = (const float*)d_in[5];
    const float* bc  = (const float*)d_in[6];
    const float* Wo  = (const float*)d_in[7];
    const float* bo  = (const float*)d_in[8];
    const float* Wfc = (const float*)d_in[9];
    const float* bfc = (const float*)d_in[10];
    float* out = (float*)d_out;

    init_state_kernel<<<128, 256>>>();

    // Phase 1: x-part of all 4 gates, all timesteps (fully parallel)
    gx_gemm<<<dim3(64, 256), 256>>>(x, Wf, Wi, Wc, Wo, bf, bi, bc, bo);

    // Phase 2: 512 sequential recurrent steps (stream-ordered kernel nodes)
    for (int t = 0; t < S_; ++t)
        lstm_step<<<128, 256>>>(t, Wf, Wi, Wc, Wo);

    // Phase 3: output projection
    fc_gemm<<<dim3(16, 256), 256>>>(Wfc, bfc, out);
}

// round 13
// speedup vs baseline: 2.3893x; 2.3893x over previous
#include <cuda_runtime.h>
#include <math.h>

#define B_    32
#define S_    512
#define IN_   1024
#define H_    1024
#define OUT_  1024
#define G4_   4096   // 4*H
#define NBLK  128

// ---------------- scratch (device globals; no allocation allowed) ----------
__device__ float g_GX[(size_t)S_ * B_ * G4_];   // [t][b][4H] pre-activations from x-part (+bias)
__device__ float g_HS[(size_t)B_ * S_ * H_];    // [b][t][H]  hidden outputs
__device__ float g_hbuf[2][B_ * H_];            // double-buffered h
__device__ float g_c[B_ * H_];                  // cell state
__device__ unsigned g_bar;                      // grid barrier counter

// ---------------- f32x2 packed helpers ------------------------------------
__device__ __forceinline__ unsigned long long splat2(float v) {
    unsigned long long r;
    asm("mov.b64 %0, {%1, %1};" : "=l"(r) : "f"(v));
    return r;
}
__device__ __forceinline__ void fma2(unsigned long long& d, unsigned long long a, unsigned long long b) {
    asm("fma.rn.f32x2 %0, %1, %2, %0;" : "+l"(d) : "l"(a), "l"(b));
}
__device__ __forceinline__ float2 unpack2(unsigned long long v) {
    float2 r;
    asm("mov.b64 {%0, %1}, %2;" : "=f"(r.x), "=f"(r.y) : "l"(v));
    return r;
}

// ---------------- init: zero h0, c0, barrier -------------------------------
__global__ void init_state_kernel() {
    int i = blockIdx.x * blockDim.x + threadIdx.x;
    if (i < B_ * H_) {
        g_hbuf[0][i] = 0.0f;
        g_c[i] = 0.0f;
    }
    if (i == 0) g_bar = 0u;
}

// ---------------- Phase 1: GX[t*32+b][n] = x[b,t,:] @ Wx[n,:].T + bias[n] --
__global__ __launch_bounds__(256) void gx_gemm(
    const float* __restrict__ x,
    const float* __restrict__ Wf, const float* __restrict__ Wi,
    const float* __restrict__ Wc, const float* __restrict__ Wo,
    const float* __restrict__ bf, const float* __restrict__ bi,
    const float* __restrict__ bc, const float* __restrict__ bo)
{
    __shared__ float As[16][68];
    __shared__ float Bs[16][68];

    const int tid = threadIdx.x;
    const int m0 = blockIdx.y * 64;
    const int n0 = blockIdx.x * 64;
    const int tx = tid & 15;
    const int ty = tid >> 4;

    const int lrow = tid >> 2;
    const int lkq  = (tid & 3) * 4;

    const int nl = n0 + lrow;
    const int gg = nl >> 10;
    const int jw = nl & 1023;
    const float* Wg = (gg == 0) ? Wf : ((gg == 1) ? Wi : ((gg == 2) ? Wc : Wo));
    const float* wrow = Wg + (size_t)jw * 2048 + 1024;   // x-part columns
    const float* arow = x + (size_t)(m0 + lrow) * 1024;

    unsigned long long acc[4][2];
#pragma unroll
    for (int r = 0; r < 4; ++r) { acc[r][0] = 0ull; acc[r][1] = 0ull; }

    for (int k0 = 0; k0 < 1024; k0 += 16) {
        float4 av = *(const float4*)(arow + k0 + lkq);
        float4 bv = *(const float4*)(wrow + k0 + lkq);
        As[lkq + 0][lrow] = av.x; As[lkq + 1][lrow] = av.y;
        As[lkq + 2][lrow] = av.z; As[lkq + 3][lrow] = av.w;
        Bs[lkq + 0][lrow] = bv.x; Bs[lkq + 1][lrow] = bv.y;
        Bs[lkq + 2][lrow] = bv.z; Bs[lkq + 3][lrow] = bv.w;
        __syncthreads();
#pragma unroll
        for (int k = 0; k < 16; ++k) {
            float4 a4 = *(const float4*)&As[k][ty * 4];
            ulonglong2 b2 = *(const ulonglong2*)&Bs[k][tx * 4];
            unsigned long long a0 = splat2(a4.x);
            unsigned long long a1 = splat2(a4.y);
            unsigned long long a2 = splat2(a4.z);
            unsigned long long a3 = splat2(a4.w);
            fma2(acc[0][0], a0, b2.x); fma2(acc[0][1], a0, b2.y);
            fma2(acc[1][0], a1, b2.x); fma2(acc[1][1], a1, b2.y);
            fma2(acc[2][0], a2, b2.x); fma2(acc[2][1], a2, b2.y);
            fma2(acc[3][0], a3, b2.x); fma2(acc[3][1], a3, b2.y);
        }
        __syncthreads();
    }

    float bias[4];
#pragma unroll
    for (int c = 0; c < 4; ++c) {
        int n = n0 + tx * 4 + c;
        int g2 = n >> 10, j2 = n & 1023;
        const float* bb = (g2 == 0) ? bf : ((g2 == 1) ? bi : ((g2 == 2) ? bc : bo));
        bias[c] = bb[j2];
    }
#pragma unroll
    for (int r = 0; r < 4; ++r) {
        int m = m0 + ty * 4 + r;
        int b  = m >> 9;
        int tt = m & 511;
        size_t row = (size_t)tt * B_ + b;
        float2 p0 = unpack2(acc[r][0]);
        float2 p1 = unpack2(acc[r][1]);
        float4 v = make_float4(p0.x + bias[0], p0.y + bias[1],
                               p1.x + bias[2], p1.y + bias[3]);
        *(float4*)&g_GX[row * G4_ + n0 + tx * 4] = v;
    }
}

// ---------------- Phase 2: persistent recurrent kernel ---------------------
// 128 blocks (block bk owns hidden cols j in [bk*8, bk*8+8), all 4 gates),
// 256 threads = 8 warps (kg = k-slice of 128) x 32 lanes (out = (gate, jj)).
// Each thread holds its 128 recurrent weights in 32 ulonglong2 REGISTERS for
// the whole sequence. Per step: warp stages its 16KB h-slice into smem,
// computes 32 batches x 1 output over its k-slice with f32x2 FMAs (h via
// conflict-free LDS.128 broadcast), reduces across kg through padded smem,
// applies the cell update, then crosses a release/acquire grid barrier.
__global__ __launch_bounds__(256, 1) void lstm_persistent(
    const float* __restrict__ Wf, const float* __restrict__ Wi,
    const float* __restrict__ Wc, const float* __restrict__ Wo)
{
    extern __shared__ float sm[];
    float* hs  = sm;                    // [32][1024]          = 32768 floats
    float* red = sm + 32768;            // [8 kg][32 out][9]   =  2304 floats
    float* pre = sm + 32768 + 2304;     // [4 g][32 b][8 jj]   =  1024 floats

    const int tid  = threadIdx.x;
    const int kg   = tid >> 5;          // warp id = k-slice (0..7)
    const int lane = tid & 31;          // out = (g, jj)
    const int g    = lane >> 3;
    const int jj   = lane & 7;
    const int j    = blockIdx.x * 8 + jj;

    // --- pin this thread's recurrent weights in registers -------------------
    const float* Wg = (g == 0) ? Wf : ((g == 1) ? Wi : ((g == 2) ? Wc : Wo));
    const float* wrow = Wg + (size_t)j * 2048 + kg * 128;   // h-part cols
    ulonglong2 w[32];
#pragma unroll
    for (int q = 0; q < 32; ++q)
        w[q] = ((const ulonglong2*)wrow)[q];

    const unsigned long long barAddr = (unsigned long long)&g_bar;

    for (int t = 0; t < S_; ++t) {
        const float* __restrict__ hin  = g_hbuf[t & 1];
        float* __restrict__       hout = g_hbuf[(t + 1) & 1];

        // --- warp stages its own k-slice of h(t): 32 rows x 128 floats ------
        {
            const float* src = hin + kg * 128 + (lane << 2);
            float* dst = hs + kg * 128 + (lane << 2);
#pragma unroll 4
            for (int r = 0; r < 32; ++r)
                *(float4*)(dst + r * 1024) = *(const float4*)(src + r * 1024);
        }
        __syncwarp();

#pragma unroll 1
        for (int bb = 0; bb < 4; ++bb) {
            unsigned long long acc[8];
#pragma unroll
            for (int i = 0; i < 8; ++i) acc[i] = 0ull;

            const float* hsb = hs + (bb * 8) * 1024 + kg * 128;
#pragma unroll
            for (int q = 0; q < 32; ++q) {
                ulonglong2 wq = w[q];
#pragma unroll
                for (int i = 0; i < 8; ++i) {
                    ulonglong2 h2 = *(const ulonglong2*)(hsb + i * 1024 + (q << 2));
                    fma2(acc[i], h2.x, wq.x);
                    fma2(acc[i], h2.y, wq.y);
                }
            }
#pragma unroll
            for (int i = 0; i < 8; ++i) {
                float2 p = unpack2(acc[i]);
                red[kg * 288 + lane * 9 + i] = p.x + p.y;
            }
            __syncthreads();

            // reduce across the 8 k-slices; fold in GX (x-part + bias)
            {
                int out = tid & 31, bi = tid >> 5;
                float s = 0.0f;
#pragma unroll
                for (int kk = 0; kk < 8; ++kk)
                    s += red[kk * 288 + out * 9 + bi];
                int gg2 = out >> 3, jj2 = out & 7;
                int b = bb * 8 + bi;
                float gx = g_GX[(size_t)t * (B_ * G4_) + (size_t)b * G4_
                                + gg2 * 1024 + blockIdx.x * 8 + jj2];
                pre[gg2 * 256 + b * 8 + jj2] = s + gx;
            }
            __syncthreads();
        }

        // --- cell update: one (b, j) per thread ------------------------------
        {
            int b2  = tid >> 3;
            int jj2 = tid & 7;
            int j2  = blockIdx.x * 8 + jj2;
            float pf = pre[0 * 256 + b2 * 8 + jj2];
            float pi = pre[1 * 256 + b2 * 8 + jj2];
            float pc = pre[2 * 256 + b2 * 8 + jj2];
            float po = pre[3 * 256 + b2 * 8 + jj2];
            float fg = 1.0f / (1.0f + expf(-pf));
            float ig = 1.0f / (1.0f + expf(-pi));
            float cg = tanhf(pc);
            float og = 1.0f / (1.0f + expf(-po));
            float cold = g_c[b2 * H_ + j2];
            float cn = fg * cold + ig * cg;
            float hn = og * tanhf(cn);
            g_c[b2 * H_ + j2]  = cn;
            hout[b2 * H_ + j2] = hn;
            g_HS[((size_t)b2 * S_ + t) * H_ + j2] = hn;
        }

        // --- grid barrier (all 128 blocks co-resident) -----------------------
        __syncthreads();
        if (tid == 0) {
            asm volatile("fence.acq_rel.gpu;" ::: "memory");      // release h/c writes
            asm volatile("red.global.gpu.add.u32 [%0], 1;"
                         :: "l"(barAddr) : "memory");
            unsigned target = (unsigned)NBLK * (unsigned)(t + 1);
            unsigned v;
            do {
                asm volatile("ld.global.acquire.gpu.u32 %0, [%1];"
                             : "=r"(v) : "l"(barAddr) : "memory");
            } while (v < target);
        }
        __syncthreads();
    }
}

// ---------------- Phase 3: out[m][n] = HS[m,:] @ Wfc[n,:].T + bfc[n] --------
__global__ __launch_bounds__(256) void fc_gemm(
    const float* __restrict__ Wfc, const float* __restrict__ bfc,
    float* __restrict__ out)
{
    __shared__ float As[16][68];
    __shared__ float Bs[16][68];

    const int tid = threadIdx.x;
    const int m0 = blockIdx.y * 64;
    const int n0 = blockIdx.x * 64;
    const int tx = tid & 15;
    const int ty = tid >> 4;

    const int lrow = tid >> 2;
    const int lkq  = (tid & 3) * 4;

    const float* wrow = Wfc + (size_t)(n0 + lrow) * 1024;
    const float* arow = g_HS + (size_t)(m0 + lrow) * 1024;

    unsigned long long acc[4][2];
#pragma unroll
    for (int r = 0; r < 4; ++r) { acc[r][0] = 0ull; acc[r][1] = 0ull; }

    for (int k0 = 0; k0 < 1024; k0 += 16) {
        float4 av = *(const float4*)(arow + k0 + lkq);
        float4 bv = *(const float4*)(wrow + k0 + lkq);
        As[lkq + 0][lrow] = av.x; As[lkq + 1][lrow] = av.y;
        As[lkq + 2][lrow] = av.z; As[lkq + 3][lrow] = av.w;
        Bs[lkq + 0][lrow] = bv.x; Bs[lkq + 1][lrow] = bv.y;
        Bs[lkq + 2][lrow] = bv.z; Bs[lkq + 3][lrow] = bv.w;
        __syncthreads();
#pragma unroll
        for (int k = 0; k < 16; ++k) {
            float4 a4 = *(const float4*)&As[k][ty * 4];
            ulonglong2 b2 = *(const ulonglong2*)&Bs[k][tx * 4];
            unsigned long long a0 = splat2(a4.x);
            unsigned long long a1 = splat2(a4.y);
            unsigned long long a2 = splat2(a4.z);
            unsigned long long a3 = splat2(a4.w);
            fma2(acc[0][0], a0, b2.x); fma2(acc[0][1], a0, b2.y);
            fma2(acc[1][0], a1, b2.x); fma2(acc[1][1], a1, b2.y);
            fma2(acc[2][0], a2, b2.x); fma2(acc[2][1], a2, b2.y);
            fma2(acc[3][0], a3, b2.x); fma2(acc[3][1], a3, b2.y);
        }
        __syncthreads();
    }

    float bias[4];
#pragma unroll
    for (int c = 0; c < 4; ++c) bias[c] = bfc[n0 + tx * 4 + c];

#pragma unroll
    for (int r = 0; r < 4; ++r) {
        int m = m0 + ty * 4 + r;
        float2 p0 = unpack2(acc[r][0]);
        float2 p1 = unpack2(acc[r][1]);
        float4 v = make_float4(p0.x + bias[0], p0.y + bias[1],
                               p1.x + bias[2], p1.y + bias[3]);
        *(float4*)&out[(size_t)m * OUT_ + n0 + tx * 4] = v;
    }
}

// ---------------- launch ----------------------------------------------------
extern "C" void kernel_launch(void* const* d_in, const int* in_sizes, int n_in,
                              void* d_out, int out_size) {
    (void)in_sizes; (void)n_in; (void)out_size;
    const float* x   = (const float*)d_in[0];
    const float* Wf  = (const float*)d_in[1];
    const float* bf  = (const float*)d_in[2];
    const float* Wi  = (const float*)d_in[3];
    const float* bi  = (const float*)d_in[4];
    const float* Wc  = (const float*)d_in[5];
    const float* bc  = (const float*)d_in[6];
    const float* Wo  = (const float*)d_in[7];
    const float* bo  = (const float*)d_in[8];
    const float* Wfc = (const float*)d_in[9];
    const float* bfc = (const float*)d_in[10];
    float* out = (float*)d_out;

    const int smemBytes = (32768 + 2304 + 1024) * (int)sizeof(float); // 144,384 B
    cudaFuncSetAttribute(lstm_persistent,
                         cudaFuncAttributeMaxDynamicSharedMemorySize, smemBytes);

    init_state_kernel<<<128, 256>>>();

    // Phase 1: x-part of all 4 gates, all timesteps (fully parallel)
    gx_gemm<<<dim3(64, 256), 256>>>(x, Wf, Wi, Wc, Wo, bf, bi, bc, bo);

    // Phase 2: one persistent kernel for all 512 recurrent steps
    lstm_persistent<<<NBLK, 256, smemBytes>>>(Wf, Wi, Wc, Wo);

    // Phase 3: output projection
    fc_gemm<<<dim3(16, 256), 256>>>(Wfc, bfc, out);
}